// round 1
// baseline (speedup 1.0000x reference)
#include <cuda_runtime.h>
#include <math.h>

#define BATCH 2
#define LSEQ  1024
#define DM    1024
#define DI    2048
#define NST   16
#define RK    64
#define DBC_W (RK + 2*NST)   /* 96 */
#define NL    4

// ---------------- scratch (device globals: no allocation allowed) ----------
__device__ float g_x    [BATCH*LSEQ*DM];     // running residual stream
__device__ float g_h    [BATCH*LSEQ*DM];     // rmsnorm output
__device__ float g_xz   [BATCH*LSEQ*2*DI];   // in-proj output (xi | z)
__device__ float g_xc   [BATCH*LSEQ*DI];     // conv+silu output
__device__ float g_dbc  [BATCH*LSEQ*DBC_W];  // [dt_low | B | C]
__device__ float g_delta[BATCH*LSEQ*DI];     // softplus(dt)
__device__ float g_u    [BATCH*LSEQ*DI];     // y * silu(z)

// ---------------- helpers ---------------------------------------------------
__device__ __forceinline__ float siluf(float v) {
    return v / (1.f + __expf(-v));
}
__device__ __forceinline__ float softplusf(float v) {
    return (v > 20.f) ? v : log1pf(__expf(v));
}

// ---------------- copy input residual --------------------------------------
__global__ void copy_in_k(const float* __restrict__ x) {
    int i = blockIdx.x * blockDim.x + threadIdx.x;
    if (i < BATCH*LSEQ*DM) g_x[i] = x[i];
}

// ---------------- RMSNorm ----------------------------------------------------
__global__ void rmsnorm_k(const float* __restrict__ w) {
    int row = blockIdx.x;                      // 0 .. BATCH*LSEQ-1
    const float* xr = g_x + row * DM;
    __shared__ float red[256];
    float s = 0.f;
    for (int i = threadIdx.x; i < DM; i += 256) { float v = xr[i]; s += v * v; }
    red[threadIdx.x] = s;
    __syncthreads();
    for (int off = 128; off > 0; off >>= 1) {
        if (threadIdx.x < off) red[threadIdx.x] += red[threadIdx.x + off];
        __syncthreads();
    }
    float inv = rsqrtf(red[0] * (1.f / DM) + 1e-5f);
    float* hr = g_h + row * DM;
    for (int i = threadIdx.x; i < DM; i += 256) hr[i] = xr[i] * inv * w[i];
}

// ---------------- tiled NT SGEMM: C[m,n] = sum_k A[m,k]*B[n,k] (+epilogue) --
// epi: 0 = plain store, 1 = softplus(acc + bias[n]), 2 = acc + resid[m*ldc+n]
__global__ __launch_bounds__(256) void sgemm_nt_k(
    const float* __restrict__ A, int lda,
    const float* __restrict__ B, int ldb,
    float* __restrict__ C, int ldc,
    const float* __restrict__ bias,
    const float* __restrict__ resid,
    int M, int N, int K, int epi)
{
    const int BM = 64, BN = 64, BK = 16;
    __shared__ float As[BK][BM + 1];
    __shared__ float Bs[BK][BN + 1];

    int tx = threadIdx.x & 15;
    int ty = threadIdx.x >> 4;
    int tid = threadIdx.x;
    int m0 = blockIdx.y * BM;
    int n0 = blockIdx.x * BN;

    float acc[4][4];
#pragma unroll
    for (int i = 0; i < 4; i++)
#pragma unroll
        for (int j = 0; j < 4; j++) acc[i][j] = 0.f;

    for (int k0 = 0; k0 < K; k0 += BK) {
        // load A tile (BM x BK), coalesced over k
#pragma unroll
        for (int i = tid; i < BM * BK; i += 256) {
            int r = i / BK, c = i % BK;
            int gm = m0 + r, gk = k0 + c;
            As[c][r] = (gm < M && gk < K) ? A[(size_t)gm * lda + gk] : 0.f;
        }
        // load B tile (BN x BK)
#pragma unroll
        for (int i = tid; i < BN * BK; i += 256) {
            int r = i / BK, c = i % BK;
            int gn = n0 + r, gk = k0 + c;
            Bs[c][r] = (gn < N && gk < K) ? B[(size_t)gn * ldb + gk] : 0.f;
        }
        __syncthreads();

#pragma unroll
        for (int kk = 0; kk < BK; kk++) {
            float a[4], bv[4];
#pragma unroll
            for (int i = 0; i < 4; i++) a[i] = As[kk][ty + 16 * i];
#pragma unroll
            for (int j = 0; j < 4; j++) bv[j] = Bs[kk][tx + 16 * j];
#pragma unroll
            for (int i = 0; i < 4; i++)
#pragma unroll
                for (int j = 0; j < 4; j++) acc[i][j] = fmaf(a[i], bv[j], acc[i][j]);
        }
        __syncthreads();
    }

#pragma unroll
    for (int i = 0; i < 4; i++) {
        int m = m0 + ty + 16 * i;
        if (m >= M) continue;
#pragma unroll
        for (int j = 0; j < 4; j++) {
            int n = n0 + tx + 16 * j;
            if (n >= N) continue;
            float v = acc[i][j];
            if (epi == 1)      v = softplusf(v + bias[n]);
            else if (epi == 2) v = v + resid[(size_t)m * ldc + n];
            C[(size_t)m * ldc + n] = v;
        }
    }
}

// ---------------- causal depthwise conv1d (k=4) + SiLU ----------------------
__global__ void conv_silu_k(const float* __restrict__ cw, const float* __restrict__ cb) {
    int idx = blockIdx.x * blockDim.x + threadIdx.x;
    if (idx >= BATCH * LSEQ * DI) return;
    int d = idx % DI;
    int l = (idx / DI) % LSEQ;
    int b = idx / (DI * LSEQ);
    float acc = cb[d];
#pragma unroll
    for (int k = 0; k < 4; k++) {
        int ls = l - 3 + k;
        if (ls >= 0)
            acc = fmaf(g_xz[((size_t)(b * LSEQ + ls)) * (2 * DI) + d], cw[d * 4 + k], acc);
    }
    g_xc[idx] = siluf(acc);
}

// ---------------- selective scan: 16 lanes per (b,d) channel ----------------
// thread t -> n = t&15 (state idx), p = t>>4, d = p%DI, b = p/DI
__global__ void scan_k(const float* __restrict__ A_log, const float* __restrict__ Dw) {
    int t = blockIdx.x * blockDim.x + threadIdx.x;
    int n = t & 15;
    int p = t >> 4;
    if (p >= BATCH * DI) return;
    int d = p % DI;
    int b = p / DI;

    float A  = -__expf(A_log[d * NST + n]);
    float Dd = Dw[d];
    float h  = 0.f;

    size_t rowD  = (size_t)(b * LSEQ) * DI + d;
    size_t row96 = (size_t)(b * LSEQ) * DBC_W;
    size_t rowZ  = (size_t)(b * LSEQ) * (2 * DI) + DI + d;

    for (int l = 0; l < LSEQ; l++) {
        float dt = g_delta[rowD];
        float xv = g_xc[rowD];
        float Bn = g_dbc[row96 + RK + n];
        float Cn = g_dbc[row96 + RK + NST + n];

        h = fmaf(__expf(dt * A), h, dt * xv * Bn);

        float y = h * Cn;
        y += __shfl_xor_sync(0xffffffffu, y, 8);
        y += __shfl_xor_sync(0xffffffffu, y, 4);
        y += __shfl_xor_sync(0xffffffffu, y, 2);
        y += __shfl_xor_sync(0xffffffffu, y, 1);

        if (n == 0) {
            float zv = g_xz[rowZ];
            g_u[rowD] = (y + Dd * xv) * siluf(zv);
        }
        rowD  += DI;
        row96 += DBC_W;
        rowZ  += 2 * DI;
    }
}

// ---------------- host orchestration ----------------------------------------
extern "C" void kernel_launch(void* const* d_in, const int* in_sizes, int n_in,
                              void* d_out, int out_size) {
    const float* x      = (const float*)d_in[0];
    const float* norm_w = (const float*)d_in[1];
    const float* W_in   = (const float*)d_in[2];
    const float* conv_w = (const float*)d_in[3];
    const float* conv_b = (const float*)d_in[4];
    const float* W_x    = (const float*)d_in[5];
    const float* W_dt   = (const float*)d_in[6];
    const float* b_dt   = (const float*)d_in[7];
    const float* A_log  = (const float*)d_in[8];
    const float* Dpar   = (const float*)d_in[9];
    const float* W_out  = (const float*)d_in[10];
    float* out = (float*)d_out;

    float *px, *ph, *pxz, *pxc, *pdbc, *pdelta, *pu;
    cudaGetSymbolAddress((void**)&px,     g_x);
    cudaGetSymbolAddress((void**)&ph,     g_h);
    cudaGetSymbolAddress((void**)&pxz,    g_xz);
    cudaGetSymbolAddress((void**)&pxc,    g_xc);
    cudaGetSymbolAddress((void**)&pdbc,   g_dbc);
    cudaGetSymbolAddress((void**)&pdelta, g_delta);
    cudaGetSymbolAddress((void**)&pu,     g_u);

    const int M = BATCH * LSEQ;  // 2048
    dim3 blk(256);
    dim3 thr2d(256);

    copy_in_k<<<(BATCH*LSEQ*DM + 255) / 256, 256>>>(x);

    for (int l = 0; l < NL; l++) {
        // 1) RMSNorm
        rmsnorm_k<<<M, 256>>>(norm_w + (size_t)l * DM);

        // 2) xz = h @ W_in^T   [M, 2*DI]
        {
            dim3 g((2 * DI) / 64, M / 64);
            sgemm_nt_k<<<g, thr2d>>>(ph, DM, W_in + (size_t)l * 2 * DI * DM, DM,
                                     pxz, 2 * DI, nullptr, nullptr,
                                     M, 2 * DI, DM, 0);
        }

        // 3) conv1d + silu -> xc
        conv_silu_k<<<(BATCH*LSEQ*DI + 255) / 256, 256>>>(
            conv_w + (size_t)l * DI * 4, conv_b + (size_t)l * DI);

        // 4) dbc = xc @ W_x^T   [M, 96]
        {
            dim3 g((DBC_W + 63) / 64, M / 64);
            sgemm_nt_k<<<g, thr2d>>>(pxc, DI, W_x + (size_t)l * DBC_W * DI, DI,
                                     pdbc, DBC_W, nullptr, nullptr,
                                     M, DBC_W, DI, 0);
        }

        // 5) delta = softplus(dbc[:, :64] @ W_dt^T + b_dt)   [M, DI]
        {
            dim3 g(DI / 64, M / 64);
            sgemm_nt_k<<<g, thr2d>>>(pdbc, DBC_W, W_dt + (size_t)l * DI * RK, RK,
                                     pdelta, DI, b_dt + (size_t)l * DI, nullptr,
                                     M, DI, RK, 1);
        }

        // 6) selective scan -> u = (C.h + D*x) * silu(z)
        scan_k<<<(BATCH * DI * NST) / 256, 256>>>(
            A_log + (size_t)l * DI * NST, Dpar + (size_t)l * DI);

        // 7) x = x + u @ W_out^T   [M, DM]
        {
            float* Cout = (l == NL - 1) ? out : px;
            dim3 g(DM / 64, M / 64);
            sgemm_nt_k<<<g, thr2d>>>(pu, DI, W_out + (size_t)l * DM * DI, DI,
                                     Cout, DM, nullptr, px,
                                     M, DM, DI, 2);
        }
    }
}

// round 2
// speedup vs baseline: 1.6361x; 1.6361x over previous
#include <cuda_runtime.h>
#include <math.h>
#include <stdint.h>

#define BATCH 2
#define LSEQ  1024
#define DM    1024
#define DI    2048
#define NST   16
#define RK    64
#define DBC_W (RK + 2*NST)   /* 96 */
#define NL    4

// ---------------- scratch (device globals: no allocation allowed) ----------
__device__ float g_x    [BATCH*LSEQ*DM];
__device__ float g_h    [BATCH*LSEQ*DM];
__device__ float g_xz   [BATCH*LSEQ*2*DI];
__device__ float g_xc   [BATCH*LSEQ*DI];
__device__ float g_dbc  [BATCH*LSEQ*DBC_W];
__device__ float g_delta[BATCH*LSEQ*DI];
__device__ float g_u    [BATCH*LSEQ*DI];

// ---------------- helpers ---------------------------------------------------
__device__ __forceinline__ float siluf(float v) {
    return v / (1.f + __expf(-v));
}
__device__ __forceinline__ float softplusf(float v) {
    return (v > 20.f) ? v : log1pf(__expf(v));
}
__device__ __forceinline__ uint32_t to_tf32(float f) {
    uint32_t u;
    asm("cvt.rna.tf32.f32 %0, %1;" : "=r"(u) : "f"(f));
    return u;
}

// ---------------- copy input residual --------------------------------------
__global__ void copy_in_k(const float* __restrict__ x) {
    int i = blockIdx.x * blockDim.x + threadIdx.x;
    if (i < BATCH*LSEQ*DM) g_x[i] = x[i];
}

// ---------------- RMSNorm ----------------------------------------------------
__global__ void rmsnorm_k(const float* __restrict__ w) {
    int row = blockIdx.x;
    const float* xr = g_x + row * DM;
    __shared__ float red[256];
    float s = 0.f;
    for (int i = threadIdx.x; i < DM; i += 256) { float v = xr[i]; s += v * v; }
    red[threadIdx.x] = s;
    __syncthreads();
    for (int off = 128; off > 0; off >>= 1) {
        if (threadIdx.x < off) red[threadIdx.x] += red[threadIdx.x + off];
        __syncthreads();
    }
    float inv = rsqrtf(red[0] * (1.f / DM) + 1e-5f);
    float* hr = g_h + row * DM;
    for (int i = threadIdx.x; i < DM; i += 256) hr[i] = xr[i] * inv * w[i];
}

// ---------------- TF32 tensor-core NT GEMM ---------------------------------
// C[m,n] = sum_k A[m,k] * B[n,k]  (+ epilogue)
// epi: 0 = plain, 1 = softplus(acc + bias[n]), 2 = acc + resid[m*ldc+n]
// Block tile 128x128x32, 8 warps, warp tile 64x32, mma.m16n8k8 tf32.
#define BMT 128
#define BNT 128
#define BKT 32
#define SSTR 36   // smem row stride (floats): (4*row + k) mod 32 hits all banks

__global__ __launch_bounds__(256) void tf32gemm_nt_k(
    const float* __restrict__ A, int lda,
    const float* __restrict__ B, int ldb,
    float* __restrict__ C, int ldc,
    const float* __restrict__ bias,
    const float* __restrict__ resid,
    int M, int N, int K, int epi)
{
    __shared__ uint32_t As[BMT * SSTR];
    __shared__ uint32_t Bs[BNT * SSTR];

    const int tid  = threadIdx.x;
    const int warp = tid >> 5;
    const int lane = tid & 31;
    const int m0 = blockIdx.y * BMT;
    const int n0 = blockIdx.x * BNT;

    const int wm = (warp >> 2) * 64;   // warp row offset within block tile
    const int wn = (warp & 3) * 32;    // warp col offset

    float c[4][4][4];
#pragma unroll
    for (int i = 0; i < 4; i++)
#pragma unroll
        for (int j = 0; j < 4; j++)
#pragma unroll
            for (int r = 0; r < 4; r++) c[i][j][r] = 0.f;

    // global-load addressing: each thread loads float4; 8 threads per 32-wide k row
    const int lr = tid >> 3;          // 0..31 (row within tile, step 32)
    const int lc = (tid & 7) << 2;    // 0,4,...,28 (k col)

    for (int k0 = 0; k0 < K; k0 += BKT) {
        // ---- load A tile (BMT x BKT) ----
#pragma unroll
        for (int i = 0; i < 4; i++) {
            int r  = lr + i * 32;
            int gm = m0 + r;
            float4 v = make_float4(0.f, 0.f, 0.f, 0.f);
            if (gm < M) v = *(const float4*)(A + (size_t)gm * lda + (k0 + lc));
            uint32_t* dst = &As[r * SSTR + lc];
            dst[0] = to_tf32(v.x); dst[1] = to_tf32(v.y);
            dst[2] = to_tf32(v.z); dst[3] = to_tf32(v.w);
        }
        // ---- load B tile (BNT x BKT) ----
#pragma unroll
        for (int i = 0; i < 4; i++) {
            int r  = lr + i * 32;
            int gn = n0 + r;
            float4 v = make_float4(0.f, 0.f, 0.f, 0.f);
            if (gn < N) v = *(const float4*)(B + (size_t)gn * ldb + (k0 + lc));
            uint32_t* dst = &Bs[r * SSTR + lc];
            dst[0] = to_tf32(v.x); dst[1] = to_tf32(v.y);
            dst[2] = to_tf32(v.z); dst[3] = to_tf32(v.w);
        }
        __syncthreads();

#pragma unroll
        for (int ks = 0; ks < 4; ks++) {
            const int kb = ks * 8;
            uint32_t a[4][4];
#pragma unroll
            for (int mt = 0; mt < 4; mt++) {
                int r = wm + mt * 16 + (lane >> 2);
                int cc = kb + (lane & 3);
                a[mt][0] = As[r * SSTR + cc];
                a[mt][1] = As[(r + 8) * SSTR + cc];
                a[mt][2] = As[r * SSTR + cc + 4];
                a[mt][3] = As[(r + 8) * SSTR + cc + 4];
            }
            uint32_t b[4][2];
#pragma unroll
            for (int nt = 0; nt < 4; nt++) {
                int n  = wn + nt * 8 + (lane >> 2);
                int kk = kb + (lane & 3);
                b[nt][0] = Bs[n * SSTR + kk];
                b[nt][1] = Bs[n * SSTR + kk + 4];
            }
#pragma unroll
            for (int mt = 0; mt < 4; mt++)
#pragma unroll
                for (int nt = 0; nt < 4; nt++) {
                    asm volatile(
                        "mma.sync.aligned.m16n8k8.row.col.f32.tf32.tf32.f32 "
                        "{%0,%1,%2,%3}, {%4,%5,%6,%7}, {%8,%9}, {%0,%1,%2,%3};"
                        : "+f"(c[mt][nt][0]), "+f"(c[mt][nt][1]),
                          "+f"(c[mt][nt][2]), "+f"(c[mt][nt][3])
                        : "r"(a[mt][0]), "r"(a[mt][1]), "r"(a[mt][2]), "r"(a[mt][3]),
                          "r"(b[nt][0]), "r"(b[nt][1]));
                }
        }
        __syncthreads();
    }

    // ---- epilogue ----
#pragma unroll
    for (int mt = 0; mt < 4; mt++) {
#pragma unroll
        for (int nt = 0; nt < 4; nt++) {
            int m = m0 + wm + mt * 16 + (lane >> 2);
            int n = n0 + wn + nt * 8 + 2 * (lane & 3);
#pragma unroll
            for (int r = 0; r < 4; r++) {
                int mm = m + (r >> 1) * 8;   // c0,c1 row m; c2,c3 row m+8
                int nn = n + (r & 1);
                if (mm >= M || nn >= N) continue;
                float v = c[mt][nt][r];
                if (epi == 1)      v = softplusf(v + bias[nn]);
                else if (epi == 2) v = v + resid[(size_t)mm * ldc + nn];
                C[(size_t)mm * ldc + nn] = v;
            }
        }
    }
}

// ---------------- causal depthwise conv1d (k=4) + SiLU ----------------------
__global__ void conv_silu_k(const float* __restrict__ cw, const float* __restrict__ cb) {
    int idx = blockIdx.x * blockDim.x + threadIdx.x;
    if (idx >= BATCH * LSEQ * DI) return;
    int d = idx % DI;
    int l = (idx / DI) % LSEQ;
    int b = idx / (DI * LSEQ);
    float acc = cb[d];
#pragma unroll
    for (int k = 0; k < 4; k++) {
        int ls = l - 3 + k;
        if (ls >= 0)
            acc = fmaf(g_xz[((size_t)(b * LSEQ + ls)) * (2 * DI) + d], cw[d * 4 + k], acc);
    }
    g_xc[idx] = siluf(acc);
}

// ---------------- selective scan: 16 lanes per (b,d) channel ----------------
__global__ void scan_k(const float* __restrict__ A_log, const float* __restrict__ Dw) {
    int t = blockIdx.x * blockDim.x + threadIdx.x;
    int n = t & 15;
    int p = t >> 4;
    if (p >= BATCH * DI) return;
    int d = p % DI;
    int b = p / DI;

    float A  = -__expf(A_log[d * NST + n]);
    float Dd = Dw[d];
    float h  = 0.f;

    size_t rowD  = (size_t)(b * LSEQ) * DI + d;
    size_t row96 = (size_t)(b * LSEQ) * DBC_W;
    size_t rowZ  = (size_t)(b * LSEQ) * (2 * DI) + DI + d;

    for (int l = 0; l < LSEQ; l++) {
        float dt = g_delta[rowD];
        float xv = g_xc[rowD];
        float Bn = g_dbc[row96 + RK + n];
        float Cn = g_dbc[row96 + RK + NST + n];

        h = fmaf(__expf(dt * A), h, dt * xv * Bn);

        float y = h * Cn;
        y += __shfl_xor_sync(0xffffffffu, y, 8);
        y += __shfl_xor_sync(0xffffffffu, y, 4);
        y += __shfl_xor_sync(0xffffffffu, y, 2);
        y += __shfl_xor_sync(0xffffffffu, y, 1);

        if (n == 0) {
            float zv = g_xz[rowZ];
            g_u[rowD] = (y + Dd * xv) * siluf(zv);
        }
        rowD  += DI;
        row96 += DBC_W;
        rowZ  += 2 * DI;
    }
}

// ---------------- host orchestration ----------------------------------------
extern "C" void kernel_launch(void* const* d_in, const int* in_sizes, int n_in,
                              void* d_out, int out_size) {
    const float* x      = (const float*)d_in[0];
    const float* norm_w = (const float*)d_in[1];
    const float* W_in   = (const float*)d_in[2];
    const float* conv_w = (const float*)d_in[3];
    const float* conv_b = (const float*)d_in[4];
    const float* W_x    = (const float*)d_in[5];
    const float* W_dt   = (const float*)d_in[6];
    const float* b_dt   = (const float*)d_in[7];
    const float* A_log  = (const float*)d_in[8];
    const float* Dpar   = (const float*)d_in[9];
    const float* W_out  = (const float*)d_in[10];
    float* out = (float*)d_out;

    float *px, *ph, *pxz, *pxc, *pdbc, *pdelta, *pu;
    cudaGetSymbolAddress((void**)&px,     g_x);
    cudaGetSymbolAddress((void**)&ph,     g_h);
    cudaGetSymbolAddress((void**)&pxz,    g_xz);
    cudaGetSymbolAddress((void**)&pxc,    g_xc);
    cudaGetSymbolAddress((void**)&pdbc,   g_dbc);
    cudaGetSymbolAddress((void**)&pdelta, g_delta);
    cudaGetSymbolAddress((void**)&pu,     g_u);

    const int M = BATCH * LSEQ;  // 2048
    dim3 thr(256);

    copy_in_k<<<(BATCH*LSEQ*DM + 255) / 256, 256>>>(x);

    for (int l = 0; l < NL; l++) {
        // 1) RMSNorm
        rmsnorm_k<<<M, 256>>>(norm_w + (size_t)l * DM);

        // 2) xz = h @ W_in^T   [M, 2*DI]
        {
            dim3 g((2 * DI + BNT - 1) / BNT, (M + BMT - 1) / BMT);
            tf32gemm_nt_k<<<g, thr>>>(ph, DM, W_in + (size_t)l * 2 * DI * DM, DM,
                                      pxz, 2 * DI, nullptr, nullptr,
                                      M, 2 * DI, DM, 0);
        }

        // 3) conv1d + silu -> xc
        conv_silu_k<<<(BATCH*LSEQ*DI + 255) / 256, 256>>>(
            conv_w + (size_t)l * DI * 4, conv_b + (size_t)l * DI);

        // 4) dbc = xc @ W_x^T   [M, 96]
        {
            dim3 g((DBC_W + BNT - 1) / BNT, (M + BMT - 1) / BMT);
            tf32gemm_nt_k<<<g, thr>>>(pxc, DI, W_x + (size_t)l * DBC_W * DI, DI,
                                      pdbc, DBC_W, nullptr, nullptr,
                                      M, DBC_W, DI, 0);
        }

        // 5) delta = softplus(dbc[:, :64] @ W_dt^T + b_dt)   [M, DI]
        {
            dim3 g((DI + BNT - 1) / BNT, (M + BMT - 1) / BMT);
            tf32gemm_nt_k<<<g, thr>>>(pdbc, DBC_W, W_dt + (size_t)l * DI * RK, RK,
                                      pdelta, DI, b_dt + (size_t)l * DI, nullptr,
                                      M, DI, RK, 1);
        }

        // 6) selective scan -> u = (C.h + D*x) * silu(z)
        scan_k<<<(BATCH * DI * NST) / 256, 256>>>(
            A_log + (size_t)l * DI * NST, Dpar + (size_t)l * DI);

        // 7) x = x + u @ W_out^T   [M, DM]
        {
            float* Cout = (l == NL - 1) ? out : px;
            dim3 g((DM + BNT - 1) / BNT, (M + BMT - 1) / BMT);
            tf32gemm_nt_k<<<g, thr>>>(pu, DI, W_out + (size_t)l * DM * DI, DI,
                                      Cout, DM, nullptr, px,
                                      M, DM, DI, 2);
        }
    }
}

// round 3
// speedup vs baseline: 2.8803x; 1.7604x over previous
#include <cuda_runtime.h>
#include <math.h>
#include <stdint.h>

#define BATCH 2
#define LSEQ  1024
#define DM    1024
#define DI    2048
#define NST   16
#define RK    64
#define DBC_W (RK + 2*NST)   /* 96 */
#define NL    4
#define MROWS (BATCH*LSEQ)   /* 2048 */
#define KSPLIT 8

// ---------------- scratch (device globals: no allocation allowed) ----------
__device__ float g_x    [MROWS*DM];
__device__ float g_h    [MROWS*DM];
__device__ float g_xz   [MROWS*2*DI];
__device__ float g_xc   [MROWS*DI];
__device__ float g_dbc  [MROWS*DBC_W];
__device__ float g_part [KSPLIT*MROWS*DBC_W];
__device__ float g_delta[MROWS*DI];
__device__ float g_u    [MROWS*DI];

// ---------------- helpers ---------------------------------------------------
__device__ __forceinline__ float siluf(float v) { return v / (1.f + __expf(-v)); }
__device__ __forceinline__ float softplusf(float v) {
    return (v > 20.f) ? v : log1pf(__expf(v));
}
__device__ __forceinline__ uint32_t to_tf32(float f) {
    uint32_t u;
    asm("cvt.rna.tf32.f32 %0, %1;" : "=r"(u) : "f"(f));
    return u;
}
__device__ __forceinline__ void cp16(uint32_t s, const void* g, bool pred) {
    if (pred)
        asm volatile("cp.async.cg.shared.global [%0], [%1], 16;" :: "r"(s), "l"(g));
    else
        asm volatile("cp.async.cg.shared.global [%0], [%1], 16, 0;" :: "r"(s), "l"(g));
}

// smem layout: rows of 32 floats, XOR swizzle keeps fragment loads conflict-free
#define SSWZ(r, c) (((r) << 5) + ((c) ^ ((((r) & 7)) << 2)))
#define TILEF (128 * 32)   /* floats per (A or B) tile */

// ---------------- copy input residual --------------------------------------
__global__ void copy_in_k(const float* __restrict__ x) {
    int i = blockIdx.x * blockDim.x + threadIdx.x;
    if (i < MROWS*DM) g_x[i] = x[i];
}

// ---------------- RMSNorm ----------------------------------------------------
__global__ void rmsnorm_k(const float* __restrict__ w) {
    int row = blockIdx.x;
    const float* xr = g_x + row * DM;
    __shared__ float red[256];
    float s = 0.f;
    for (int i = threadIdx.x; i < DM; i += 256) { float v = xr[i]; s += v * v; }
    red[threadIdx.x] = s;
    __syncthreads();
    for (int off = 128; off > 0; off >>= 1) {
        if (threadIdx.x < off) red[threadIdx.x] += red[threadIdx.x + off];
        __syncthreads();
    }
    float inv = rsqrtf(red[0] * (1.f / DM) + 1e-5f);
    float* hr = g_h + row * DM;
    for (int i = threadIdx.x; i < DM; i += 256) hr[i] = xr[i] * inv * w[i];
}

// ---------------- TF32 tensor-core NT GEMM, cp.async double-buffered -------
// C[m,n] = sum_k A[m,k]*B[n,k] (+epilogue)
// epi: 0 plain, 1 softplus(acc+bias[n]), 2 acc+resid[m*ldc+n]
// split-K: blockIdx.z offsets A,B by z*kspan and C by z*cspan (K = per-split K)
__global__ __launch_bounds__(256, 2) void tf32gemm_nt_k(
    const float* __restrict__ A, int lda,
    const float* __restrict__ B, int ldb,
    float* __restrict__ C, int ldc,
    const float* __restrict__ bias,
    const float* __restrict__ resid,
    int M, int N, int K, int epi,
    int kspan, size_t cspan)
{
    extern __shared__ float smem[];
    float* As = smem;                 // [2][TILEF]
    float* Bs = smem + 2 * TILEF;     // [2][TILEF]

    A += (size_t)blockIdx.z * kspan;
    B += (size_t)blockIdx.z * kspan;
    C += (size_t)blockIdx.z * cspan;

    const int tid  = threadIdx.x;
    const int warp = tid >> 5;
    const int lane = tid & 31;
    const int m0 = blockIdx.y * 128;
    const int n0 = blockIdx.x * 128;

    const int wm = (warp >> 2) * 64;
    const int wn = (warp & 3) * 32;

    float c[4][4][4];
#pragma unroll
    for (int i = 0; i < 4; i++)
#pragma unroll
        for (int j = 0; j < 4; j++)
#pragma unroll
            for (int r = 0; r < 4; r++) c[i][j][r] = 0.f;

    const int lr = tid >> 3;          // 0..31
    const int lc = (tid & 7) << 2;    // 0,4..28
    const int nk = K >> 5;            // k-tiles of 32

    uint32_t sbase = (uint32_t)__cvta_generic_to_shared(smem);

    // ---- issue tile 0 ----
    {
        const int k0 = 0;
#pragma unroll
        for (int i = 0; i < 4; i++) {
            int r = lr + i * 32;
            uint32_t sa = sbase + (uint32_t)(SSWZ(r, lc)) * 4u;
            cp16(sa, A + (size_t)(m0 + r) * lda + k0 + lc, (m0 + r) < M);
            uint32_t sb = sbase + (uint32_t)(2 * TILEF + SSWZ(r, lc)) * 4u;
            cp16(sb, B + (size_t)(n0 + r) * ldb + k0 + lc, (n0 + r) < N);
        }
        asm volatile("cp.async.commit_group;");
    }

    for (int kt = 0; kt < nk; kt++) {
        const int buf = kt & 1;
        // ---- prefetch tile kt+1 into buf^1 ----
        if (kt + 1 < nk) {
            const int k0 = (kt + 1) << 5;
            const int ob = (buf ^ 1) * TILEF;
#pragma unroll
            for (int i = 0; i < 4; i++) {
                int r = lr + i * 32;
                uint32_t sa = sbase + (uint32_t)(ob + SSWZ(r, lc)) * 4u;
                cp16(sa, A + (size_t)(m0 + r) * lda + k0 + lc, (m0 + r) < M);
                uint32_t sb = sbase + (uint32_t)(2 * TILEF + ob + SSWZ(r, lc)) * 4u;
                cp16(sb, B + (size_t)(n0 + r) * ldb + k0 + lc, (n0 + r) < N);
            }
            asm volatile("cp.async.commit_group;");
            asm volatile("cp.async.wait_group 1;");
        } else {
            asm volatile("cp.async.wait_group 0;");
        }
        __syncthreads();

        const float* Sa = As + buf * TILEF;
        const float* Sb = Bs + buf * TILEF;

#pragma unroll
        for (int ks = 0; ks < 4; ks++) {
            const int kb = ks * 8;
            uint32_t a[4][4];
#pragma unroll
            for (int mt = 0; mt < 4; mt++) {
                int r  = wm + mt * 16 + (lane >> 2);
                int cc = kb + (lane & 3);
                a[mt][0] = to_tf32(Sa[SSWZ(r,     cc)]);
                a[mt][1] = to_tf32(Sa[SSWZ(r + 8, cc)]);
                a[mt][2] = to_tf32(Sa[SSWZ(r,     cc + 4)]);
                a[mt][3] = to_tf32(Sa[SSWZ(r + 8, cc + 4)]);
            }
            uint32_t b[4][2];
#pragma unroll
            for (int nt = 0; nt < 4; nt++) {
                int n  = wn + nt * 8 + (lane >> 2);
                int kk = kb + (lane & 3);
                b[nt][0] = to_tf32(Sb[SSWZ(n, kk)]);
                b[nt][1] = to_tf32(Sb[SSWZ(n, kk + 4)]);
            }
#pragma unroll
            for (int mt = 0; mt < 4; mt++)
#pragma unroll
                for (int nt = 0; nt < 4; nt++) {
                    asm volatile(
                        "mma.sync.aligned.m16n8k8.row.col.f32.tf32.tf32.f32 "
                        "{%0,%1,%2,%3}, {%4,%5,%6,%7}, {%8,%9}, {%0,%1,%2,%3};"
                        : "+f"(c[mt][nt][0]), "+f"(c[mt][nt][1]),
                          "+f"(c[mt][nt][2]), "+f"(c[mt][nt][3])
                        : "r"(a[mt][0]), "r"(a[mt][1]), "r"(a[mt][2]), "r"(a[mt][3]),
                          "r"(b[nt][0]), "r"(b[nt][1]));
                }
        }
        __syncthreads();
    }

    // ---- epilogue ----
#pragma unroll
    for (int mt = 0; mt < 4; mt++) {
#pragma unroll
        for (int nt = 0; nt < 4; nt++) {
            int m = m0 + wm + mt * 16 + (lane >> 2);
            int n = n0 + wn + nt * 8 + 2 * (lane & 3);
#pragma unroll
            for (int r = 0; r < 4; r++) {
                int mm = m + (r >> 1) * 8;
                int nn = n + (r & 1);
                if (mm >= M || nn >= N) continue;
                float v = c[mt][nt][r];
                if (epi == 1)      v = softplusf(v + bias[nn]);
                else if (epi == 2) v = v + resid[(size_t)mm * ldc + nn];
                C[(size_t)mm * ldc + nn] = v;
            }
        }
    }
}

// ---------------- split-K reduction for GEMM2 --------------------------------
__global__ void reduce_part_k() {
    int i = blockIdx.x * blockDim.x + threadIdx.x;
    if (i >= MROWS * DBC_W) return;
    float s = 0.f;
#pragma unroll
    for (int p = 0; p < KSPLIT; p++) s += g_part[(size_t)p * MROWS * DBC_W + i];
    g_dbc[i] = s;
}

// ---------------- causal depthwise conv1d (k=4) + SiLU ----------------------
__global__ void conv_silu_k(const float* __restrict__ cw, const float* __restrict__ cb) {
    int idx = blockIdx.x * blockDim.x + threadIdx.x;
    if (idx >= MROWS * DI) return;
    int d = idx % DI;
    int l = (idx / DI) % LSEQ;
    int b = idx / (DI * LSEQ);
    float acc = cb[d];
#pragma unroll
    for (int k = 0; k < 4; k++) {
        int ls = l - 3 + k;
        if (ls >= 0)
            acc = fmaf(g_xz[((size_t)(b * LSEQ + ls)) * (2 * DI) + d], cw[d * 4 + k], acc);
    }
    g_xc[idx] = siluf(acc);
}

// ---------------- selective scan, software-pipelined loads ------------------
__global__ void scan_k(const float* __restrict__ A_log, const float* __restrict__ Dw) {
    int t = blockIdx.x * blockDim.x + threadIdx.x;
    int n = t & 15;
    int p = t >> 4;
    if (p >= BATCH * DI) return;
    int d = p % DI;
    int b = p / DI;

    float A  = -__expf(A_log[d * NST + n]);
    float Dd = Dw[d];
    float h  = 0.f;

    size_t rowD  = (size_t)(b * LSEQ) * DI + d;
    size_t row96 = (size_t)(b * LSEQ) * DBC_W;
    size_t rowZ  = (size_t)(b * LSEQ) * (2 * DI) + DI + d;

    float dt = g_delta[rowD];
    float xv = g_xc[rowD];
    float Bn = g_dbc[row96 + RK + n];
    float Cn = g_dbc[row96 + RK + NST + n];
    float zv = g_xz[rowZ];

#pragma unroll 2
    for (int l = 0; l < LSEQ; l++) {
        size_t rowD1  = rowD + DI;
        size_t row961 = row96 + DBC_W;
        size_t rowZ1  = rowZ + 2 * DI;
        float dt1 = 0.f, xv1 = 0.f, Bn1 = 0.f, Cn1 = 0.f, zv1 = 0.f;
        if (l + 1 < LSEQ) {
            dt1 = g_delta[rowD1];
            xv1 = g_xc[rowD1];
            Bn1 = g_dbc[row961 + RK + n];
            Cn1 = g_dbc[row961 + RK + NST + n];
            zv1 = g_xz[rowZ1];
        }

        h = fmaf(__expf(dt * A), h, dt * xv * Bn);

        float y = h * Cn;
        y += __shfl_xor_sync(0xffffffffu, y, 8);
        y += __shfl_xor_sync(0xffffffffu, y, 4);
        y += __shfl_xor_sync(0xffffffffu, y, 2);
        y += __shfl_xor_sync(0xffffffffu, y, 1);

        if (n == 0) g_u[rowD] = (y + Dd * xv) * siluf(zv);

        dt = dt1; xv = xv1; Bn = Bn1; Cn = Cn1; zv = zv1;
        rowD = rowD1; row96 = row961; rowZ = rowZ1;
    }
}

// ---------------- host orchestration ----------------------------------------
extern "C" void kernel_launch(void* const* d_in, const int* in_sizes, int n_in,
                              void* d_out, int out_size) {
    const float* x      = (const float*)d_in[0];
    const float* norm_w = (const float*)d_in[1];
    const float* W_in   = (const float*)d_in[2];
    const float* conv_w = (const float*)d_in[3];
    const float* conv_b = (const float*)d_in[4];
    const float* W_x    = (const float*)d_in[5];
    const float* W_dt   = (const float*)d_in[6];
    const float* b_dt   = (const float*)d_in[7];
    const float* A_log  = (const float*)d_in[8];
    const float* Dpar   = (const float*)d_in[9];
    const float* W_out  = (const float*)d_in[10];
    float* out = (float*)d_out;

    float *px, *ph, *pxz, *pxc, *pdbc, *ppart, *pdelta, *pu;
    cudaGetSymbolAddress((void**)&px,     g_x);
    cudaGetSymbolAddress((void**)&ph,     g_h);
    cudaGetSymbolAddress((void**)&pxz,    g_xz);
    cudaGetSymbolAddress((void**)&pxc,    g_xc);
    cudaGetSymbolAddress((void**)&pdbc,   g_dbc);
    cudaGetSymbolAddress((void**)&ppart,  g_part);
    cudaGetSymbolAddress((void**)&pdelta, g_delta);
    cudaGetSymbolAddress((void**)&pu,     g_u);

    const int M = MROWS;  // 2048
    const int SMEM = 4 * TILEF * sizeof(float);  // 64 KB
    static int smem_set = 0;
    if (!smem_set) {
        cudaFuncSetAttribute(tf32gemm_nt_k,
                             cudaFuncAttributeMaxDynamicSharedMemorySize, SMEM);
        smem_set = 1;
    }

    dim3 thr(256);
    copy_in_k<<<(MROWS*DM + 255) / 256, 256>>>(x);

    for (int l = 0; l < NL; l++) {
        // 1) RMSNorm
        rmsnorm_k<<<M, 256>>>(norm_w + (size_t)l * DM);

        // 2) xz = h @ W_in^T   [M, 2*DI]
        {
            dim3 g(2 * DI / 128, M / 128, 1);
            tf32gemm_nt_k<<<g, thr, SMEM>>>(ph, DM, W_in + (size_t)l * 2 * DI * DM, DM,
                                            pxz, 2 * DI, nullptr, nullptr,
                                            M, 2 * DI, DM, 0, 0, 0);
        }

        // 3) conv1d + silu -> xc
        conv_silu_k<<<(MROWS*DI + 255) / 256, 256>>>(
            conv_w + (size_t)l * DI * 4, conv_b + (size_t)l * DI);

        // 4) dbc = xc @ W_x^T   [M, 96]  -- split-K=8 into partials, then reduce
        {
            const int Kc = DI / KSPLIT;  // 256
            dim3 g(1, M / 128, KSPLIT);
            tf32gemm_nt_k<<<g, thr, SMEM>>>(pxc, DI, W_x + (size_t)l * DBC_W * DI, DI,
                                            ppart, DBC_W, nullptr, nullptr,
                                            M, DBC_W, Kc, 0,
                                            Kc, (size_t)M * DBC_W);
            reduce_part_k<<<(MROWS * DBC_W + 255) / 256, 256>>>();
        }

        // 5) delta = softplus(dbc[:, :64] @ W_dt^T + b_dt)   [M, DI]
        {
            dim3 g(DI / 128, M / 128, 1);
            tf32gemm_nt_k<<<g, thr, SMEM>>>(pdbc, DBC_W, W_dt + (size_t)l * DI * RK, RK,
                                            pdelta, DI, b_dt + (size_t)l * DI, nullptr,
                                            M, DI, RK, 1, 0, 0);
        }

        // 6) selective scan -> u
        scan_k<<<(BATCH * DI * NST) / 256, 256>>>(
            A_log + (size_t)l * DI * NST, Dpar + (size_t)l * DI);

        // 7) x = x + u @ W_out^T   [M, DM]
        {
            float* Cout = (l == NL - 1) ? out : px;
            dim3 g(DM / 128, M / 128, 1);
            tf32gemm_nt_k<<<g, thr, SMEM>>>(pu, DI, W_out + (size_t)l * DM * DI, DI,
                                            Cout, DM, nullptr, px,
                                            M, DM, DI, 2, 0, 0);
        }
    }
}

// round 4
// speedup vs baseline: 3.4278x; 1.1901x over previous
#include <cuda_runtime.h>
#include <cuda_bf16.h>
#include <math.h>
#include <stdint.h>

#define BATCH 2
#define LSEQ  1024
#define DM    1024
#define DI    2048
#define NST   16
#define RK    64
#define DBC_W (RK + 2*NST)   /* 96 */
#define NL    4
#define MROWS (BATCH*LSEQ)   /* 2048 */
#define KSPLIT 8

typedef __nv_bfloat16 bf16;

// ---------------- fp32 scratch ----------------------------------------------
__device__ float g_x    [MROWS*DM];
__device__ float g_xz   [MROWS*2*DI];
__device__ float g_xc   [MROWS*DI];
__device__ float g_dbc  [MROWS*DBC_W];
__device__ float g_part [KSPLIT*MROWS*DBC_W];
__device__ float g_delta[MROWS*DI];

// ---------------- bf16 scratch (GEMM inputs) --------------------------------
__device__ bf16 g_h_bf  [MROWS*DM];
__device__ bf16 g_xc_bf [MROWS*DI];
__device__ bf16 g_dbc_bf[MROWS*DBC_W];
__device__ bf16 g_u_bf  [MROWS*DI];
__device__ bf16 g_Win_bf [NL*2*DI*DM];
__device__ bf16 g_Wx_bf  [NL*DBC_W*DI];
__device__ bf16 g_Wdt_bf [NL*DI*RK];
__device__ bf16 g_Wout_bf[NL*DM*DI];

// ---------------- helpers ---------------------------------------------------
__device__ __forceinline__ float siluf(float v) { return v / (1.f + __expf(-v)); }
__device__ __forceinline__ float softplusf(float v) {
    return (v > 20.f) ? v : log1pf(__expf(v));
}
__device__ __forceinline__ void cp16(uint32_t s, const void* g, bool pred) {
    if (pred)
        asm volatile("cp.async.cg.shared.global [%0], [%1], 16;" :: "r"(s), "l"(g));
    else
        asm volatile("cp.async.cg.shared.global [%0], [%1], 16, 0;" :: "r"(s), "l"(g));
}

// ---------------- fp32 -> bf16 bulk convert ---------------------------------
__global__ void f2bf_k(const float* __restrict__ s, bf16* __restrict__ d, int n) {
    int i = blockIdx.x * blockDim.x + threadIdx.x;
    for (; i < n; i += gridDim.x * blockDim.x) d[i] = __float2bfloat16(s[i]);
}

// ---------------- copy input residual ---------------------------------------
__global__ void copy_in_k(const float* __restrict__ x) {
    int i = blockIdx.x * blockDim.x + threadIdx.x;
    if (i < MROWS*DM) g_x[i] = x[i];
}

// ---------------- RMSNorm (writes bf16 h) ------------------------------------
__global__ void rmsnorm_k(const float* __restrict__ w) {
    int row = blockIdx.x;
    const float* xr = g_x + row * DM;
    __shared__ float red[256];
    float s = 0.f;
    for (int i = threadIdx.x; i < DM; i += 256) { float v = xr[i]; s += v * v; }
    red[threadIdx.x] = s;
    __syncthreads();
    for (int off = 128; off > 0; off >>= 1) {
        if (threadIdx.x < off) red[threadIdx.x] += red[threadIdx.x + off];
        __syncthreads();
    }
    float inv = rsqrtf(red[0] * (1.f / DM) + 1e-5f);
    bf16* hr = g_h_bf + (size_t)row * DM;
    for (int i = threadIdx.x; i < DM; i += 256)
        hr[i] = __float2bfloat16(xr[i] * inv * w[i]);
}

// ---------------- bf16 tensor-core NT GEMM (ldmatrix + cp.async) -----------
// C[m,n] = sum_k A[m,k]*B[n,k] (+epilogue). A,B bf16; C fp32.
// Block tile 128x128x64, 8 warps (warp 64x32), mma.m16n8k16 bf16.
// smem: 2 stages x (A 16KB + B 16KB) = 64KB. 128B rows, 16B-chunk XOR swizzle.
#define STAGEB 32768
__global__ __launch_bounds__(256, 2) void bf16gemm_nt_k(
    const bf16* __restrict__ A, int lda,
    const bf16* __restrict__ B, int ldb,
    float* __restrict__ C, int ldc,
    const float* __restrict__ bias,
    const float* __restrict__ resid,
    int M, int N, int K, int epi,
    int kspan, size_t cspan)
{
    extern __shared__ char smem[];
    A += (size_t)blockIdx.z * kspan;
    B += (size_t)blockIdx.z * kspan;
    C += (size_t)blockIdx.z * cspan;

    const int tid  = threadIdx.x;
    const int warp = tid >> 5;
    const int lane = tid & 31;
    const int m0 = blockIdx.y * 128;
    const int n0 = blockIdx.x * 128;
    const int wm = (warp >> 2) * 64;
    const int wn = (warp & 3) * 32;

    float c[4][4][4];
#pragma unroll
    for (int i = 0; i < 4; i++)
#pragma unroll
        for (int j = 0; j < 4; j++)
#pragma unroll
            for (int r = 0; r < 4; r++) c[i][j][r] = 0.f;

    const uint32_t sbase = (uint32_t)__cvta_generic_to_shared(smem);
    const int nk = K >> 6;    // k-tiles of 64

    const int lane8 = lane & 7;
    const int lmat  = lane >> 3;

    // ---- issue tile 0 ----
    {
#pragma unroll
        for (int i = 0; i < 4; i++) {
            int idx = tid + i * 256;            // 0..1023
            int r = idx >> 3, cc = idx & 7;     // row, 16B-chunk
            uint32_t so = (uint32_t)((r << 7) + ((cc ^ (r & 7)) << 4));
            cp16(sbase + so, A + (size_t)(m0 + r) * lda + cc * 8, (m0 + r) < M);
            cp16(sbase + 16384u + so, B + (size_t)(n0 + r) * ldb + cc * 8, (n0 + r) < N);
        }
        asm volatile("cp.async.commit_group;");
    }

    for (int kt = 0; kt < nk; kt++) {
        const uint32_t st = (uint32_t)(kt & 1) * STAGEB;
        if (kt + 1 < nk) {
            const int k0 = (kt + 1) << 6;
            const uint32_t st1 = (uint32_t)((kt + 1) & 1) * STAGEB;
#pragma unroll
            for (int i = 0; i < 4; i++) {
                int idx = tid + i * 256;
                int r = idx >> 3, cc = idx & 7;
                uint32_t so = st1 + (uint32_t)((r << 7) + ((cc ^ (r & 7)) << 4));
                cp16(sbase + so, A + (size_t)(m0 + r) * lda + k0 + cc * 8, (m0 + r) < M);
                cp16(sbase + 16384u + so, B + (size_t)(n0 + r) * ldb + k0 + cc * 8, (n0 + r) < N);
            }
            asm volatile("cp.async.commit_group;");
            asm volatile("cp.async.wait_group 1;");
        } else {
            asm volatile("cp.async.wait_group 0;");
        }
        __syncthreads();

        const uint32_t sA = sbase + st;
        const uint32_t sB = sA + 16384u;

#pragma unroll
        for (int ks = 0; ks < 4; ks++) {
            uint32_t a[4][4];
#pragma unroll
            for (int mt = 0; mt < 4; mt++) {
                int ar = wm + mt * 16 + ((lmat & 1) << 3) + lane8;
                int ac = (ks << 1) + (lmat >> 1);
                uint32_t addr = sA + (uint32_t)((ar << 7) + ((ac ^ (ar & 7)) << 4));
                asm volatile("ldmatrix.sync.aligned.m8n8.x4.shared.b16 {%0,%1,%2,%3}, [%4];"
                             : "=r"(a[mt][0]), "=r"(a[mt][1]), "=r"(a[mt][2]), "=r"(a[mt][3])
                             : "r"(addr));
            }
            uint32_t b[4][2];
#pragma unroll
            for (int np = 0; np < 2; np++) {
                int br = wn + np * 16 + ((lmat >> 1) << 3) + lane8;
                int bc = (ks << 1) + (lmat & 1);
                uint32_t addr = sB + (uint32_t)((br << 7) + ((bc ^ (br & 7)) << 4));
                asm volatile("ldmatrix.sync.aligned.m8n8.x4.shared.b16 {%0,%1,%2,%3}, [%4];"
                             : "=r"(b[np*2][0]), "=r"(b[np*2][1]),
                               "=r"(b[np*2+1][0]), "=r"(b[np*2+1][1])
                             : "r"(addr));
            }
#pragma unroll
            for (int mt = 0; mt < 4; mt++)
#pragma unroll
                for (int nt = 0; nt < 4; nt++) {
                    asm volatile(
                        "mma.sync.aligned.m16n8k16.row.col.f32.bf16.bf16.f32 "
                        "{%0,%1,%2,%3}, {%4,%5,%6,%7}, {%8,%9}, {%0,%1,%2,%3};"
                        : "+f"(c[mt][nt][0]), "+f"(c[mt][nt][1]),
                          "+f"(c[mt][nt][2]), "+f"(c[mt][nt][3])
                        : "r"(a[mt][0]), "r"(a[mt][1]), "r"(a[mt][2]), "r"(a[mt][3]),
                          "r"(b[nt][0]), "r"(b[nt][1]));
                }
        }
        __syncthreads();
    }

    // ---- epilogue (float2 stores) ----
#pragma unroll
    for (int mt = 0; mt < 4; mt++) {
#pragma unroll
        for (int nt = 0; nt < 4; nt++) {
            int m = m0 + wm + mt * 16 + (lane >> 2);
            int n = n0 + wn + nt * 8 + 2 * (lane & 3);
            if (n + 1 >= N && n >= N) continue;
#pragma unroll
            for (int half = 0; half < 2; half++) {
                int mm = m + half * 8;
                if (mm >= M || n >= N) continue;
                float v0 = c[mt][nt][half * 2];
                float v1 = c[mt][nt][half * 2 + 1];
                if (epi == 1) {
                    v0 = softplusf(v0 + bias[n]);
                    v1 = softplusf(v1 + bias[n + 1]);
                } else if (epi == 2) {
                    const float2 rv = *(const float2*)(resid + (size_t)mm * ldc + n);
                    v0 += rv.x; v1 += rv.y;
                }
                *(float2*)(C + (size_t)mm * ldc + n) = make_float2(v0, v1);
            }
        }
    }
}

// ---------------- split-K reduction (fp32 + bf16 out) ------------------------
__global__ void reduce_part_k() {
    int i = blockIdx.x * blockDim.x + threadIdx.x;
    if (i >= MROWS * DBC_W) return;
    float s = 0.f;
#pragma unroll
    for (int p = 0; p < KSPLIT; p++) s += g_part[(size_t)p * MROWS * DBC_W + i];
    g_dbc[i] = s;
    g_dbc_bf[i] = __float2bfloat16(s);
}

// ---------------- causal depthwise conv1d (k=4) + SiLU ----------------------
__global__ void conv_silu_k(const float* __restrict__ cw, const float* __restrict__ cb) {
    int idx = blockIdx.x * blockDim.x + threadIdx.x;
    if (idx >= MROWS * DI) return;
    int d = idx % DI;
    int l = (idx / DI) % LSEQ;
    int b = idx / (DI * LSEQ);
    float acc = cb[d];
#pragma unroll
    for (int k = 0; k < 4; k++) {
        int ls = l - 3 + k;
        if (ls >= 0)
            acc = fmaf(g_xz[((size_t)(b * LSEQ + ls)) * (2 * DI) + d], cw[d * 4 + k], acc);
    }
    float v = siluf(acc);
    g_xc[idx] = v;
    g_xc_bf[idx] = __float2bfloat16(v);
}

// ---------------- selective scan (pipelined), writes bf16 u -----------------
__global__ void scan_k(const float* __restrict__ A_log, const float* __restrict__ Dw) {
    int t = blockIdx.x * blockDim.x + threadIdx.x;
    int n = t & 15;
    int p = t >> 4;
    if (p >= BATCH * DI) return;
    int d = p % DI;
    int b = p / DI;

    float A  = -__expf(A_log[d * NST + n]);
    float Dd = Dw[d];
    float h  = 0.f;

    size_t rowD  = (size_t)(b * LSEQ) * DI + d;
    size_t row96 = (size_t)(b * LSEQ) * DBC_W;
    size_t rowZ  = (size_t)(b * LSEQ) * (2 * DI) + DI + d;

    float dt = g_delta[rowD];
    float xv = g_xc[rowD];
    float Bn = g_dbc[row96 + RK + n];
    float Cn = g_dbc[row96 + RK + NST + n];
    float zv = g_xz[rowZ];

#pragma unroll 2
    for (int l = 0; l < LSEQ; l++) {
        size_t rowD1  = rowD + DI;
        size_t row961 = row96 + DBC_W;
        size_t rowZ1  = rowZ + 2 * DI;
        float dt1 = 0.f, xv1 = 0.f, Bn1 = 0.f, Cn1 = 0.f, zv1 = 0.f;
        if (l + 1 < LSEQ) {
            dt1 = g_delta[rowD1];
            xv1 = g_xc[rowD1];
            Bn1 = g_dbc[row961 + RK + n];
            Cn1 = g_dbc[row961 + RK + NST + n];
            zv1 = g_xz[rowZ1];
        }

        h = fmaf(__expf(dt * A), h, dt * xv * Bn);

        float y = h * Cn;
        y += __shfl_xor_sync(0xffffffffu, y, 8);
        y += __shfl_xor_sync(0xffffffffu, y, 4);
        y += __shfl_xor_sync(0xffffffffu, y, 2);
        y += __shfl_xor_sync(0xffffffffu, y, 1);

        if (n == 0)
            g_u_bf[rowD] = __float2bfloat16((y + Dd * xv) * siluf(zv));

        dt = dt1; xv = xv1; Bn = Bn1; Cn = Cn1; zv = zv1;
        rowD = rowD1; row96 = row961; rowZ = rowZ1;
    }
}

// ---------------- host orchestration ----------------------------------------
extern "C" void kernel_launch(void* const* d_in, const int* in_sizes, int n_in,
                              void* d_out, int out_size) {
    const float* x      = (const float*)d_in[0];
    const float* norm_w = (const float*)d_in[1];
    const float* W_in   = (const float*)d_in[2];
    const float* conv_w = (const float*)d_in[3];
    const float* conv_b = (const float*)d_in[4];
    const float* W_x    = (const float*)d_in[5];
    const float* W_dt   = (const float*)d_in[6];
    const float* b_dt   = (const float*)d_in[7];
    const float* A_log  = (const float*)d_in[8];
    const float* Dpar   = (const float*)d_in[9];
    const float* W_out  = (const float*)d_in[10];
    float* out = (float*)d_out;

    float *px, *pxz, *pxc, *pdbc, *ppart, *pdelta;
    bf16 *ph_bf, *pxc_bf, *pdbc_bf, *pu_bf, *pWin, *pWx, *pWdt, *pWout;
    cudaGetSymbolAddress((void**)&px,     g_x);
    cudaGetSymbolAddress((void**)&pxz,    g_xz);
    cudaGetSymbolAddress((void**)&pxc,    g_xc);
    cudaGetSymbolAddress((void**)&pdbc,   g_dbc);
    cudaGetSymbolAddress((void**)&ppart,  g_part);
    cudaGetSymbolAddress((void**)&pdelta, g_delta);
    cudaGetSymbolAddress((void**)&ph_bf,  g_h_bf);
    cudaGetSymbolAddress((void**)&pxc_bf, g_xc_bf);
    cudaGetSymbolAddress((void**)&pdbc_bf,g_dbc_bf);
    cudaGetSymbolAddress((void**)&pu_bf,  g_u_bf);
    cudaGetSymbolAddress((void**)&pWin,   g_Win_bf);
    cudaGetSymbolAddress((void**)&pWx,    g_Wx_bf);
    cudaGetSymbolAddress((void**)&pWdt,   g_Wdt_bf);
    cudaGetSymbolAddress((void**)&pWout,  g_Wout_bf);

    const int M = MROWS;
    const int SMEM = 2 * STAGEB;  // 64 KB
    static int smem_set = 0;
    if (!smem_set) {
        cudaFuncSetAttribute(bf16gemm_nt_k,
                             cudaFuncAttributeMaxDynamicSharedMemorySize, SMEM);
        smem_set = 1;
    }

    dim3 thr(256);
    copy_in_k<<<(MROWS*DM + 255) / 256, 256>>>(x);

    // weights -> bf16 (once per launch)
    f2bf_k<<<1184, 256>>>(W_in,  pWin,  NL * 2 * DI * DM);
    f2bf_k<<<296,  256>>>(W_x,   pWx,   NL * DBC_W * DI);
    f2bf_k<<<296,  256>>>(W_dt,  pWdt,  NL * DI * RK);
    f2bf_k<<<1184, 256>>>(W_out, pWout, NL * DM * DI);

    for (int l = 0; l < NL; l++) {
        rmsnorm_k<<<M, 256>>>(norm_w + (size_t)l * DM);

        // 2) xz = h @ W_in^T   [M, 2*DI]
        {
            dim3 g(2 * DI / 128, M / 128, 1);
            bf16gemm_nt_k<<<g, thr, SMEM>>>(ph_bf, DM, pWin + (size_t)l * 2 * DI * DM, DM,
                                            pxz, 2 * DI, nullptr, nullptr,
                                            M, 2 * DI, DM, 0, 0, 0);
        }

        conv_silu_k<<<(MROWS*DI + 255) / 256, 256>>>(
            conv_w + (size_t)l * DI * 4, conv_b + (size_t)l * DI);

        // 4) dbc = xc @ W_x^T   [M, 96]  split-K=8 + reduce
        {
            const int Kc = DI / KSPLIT;  // 256
            dim3 g(1, M / 128, KSPLIT);
            bf16gemm_nt_k<<<g, thr, SMEM>>>(pxc_bf, DI, pWx + (size_t)l * DBC_W * DI, DI,
                                            ppart, DBC_W, nullptr, nullptr,
                                            M, DBC_W, Kc, 0,
                                            Kc, (size_t)M * DBC_W);
            reduce_part_k<<<(MROWS * DBC_W + 255) / 256, 256>>>();
        }

        // 5) delta = softplus(dbc[:, :64] @ W_dt^T + b_dt)   [M, DI]
        {
            dim3 g(DI / 128, M / 128, 1);
            bf16gemm_nt_k<<<g, thr, SMEM>>>(pdbc_bf, DBC_W, pWdt + (size_t)l * DI * RK, RK,
                                            pdelta, DI, b_dt + (size_t)l * DI, nullptr,
                                            M, DI, RK, 1, 0, 0);
        }

        scan_k<<<(BATCH * DI * NST) / 256, 256>>>(
            A_log + (size_t)l * DI * NST, Dpar + (size_t)l * DI);

        // 7) x = x + u @ W_out^T   [M, DM]
        {
            float* Cout = (l == NL - 1) ? out : px;
            dim3 g(DM / 128, M / 128, 1);
            bf16gemm_nt_k<<<g, thr, SMEM>>>(pu_bf, DI, pWout + (size_t)l * DM * DI, DI,
                                            Cout, DM, nullptr, px,
                                            M, DM, DI, 2, 0, 0);
        }
    }
}